// round 13
// baseline (speedup 1.0000x reference)
#include <cuda_runtime.h>
#include <math.h>

#define NTOK 65536
#define CODES_OFF 33554432
#define LAT_OFF   34144256
#define COMMIT_OFF 38862848

// ---------------- device scratch (no allocation) ----------------
__device__ float g_P[72 * NTOK];      // [q][tok], q = i*8+d
__device__ float g_Q[72 * NTOK];      // selected raw code vecs, [q][tok]
__device__ float g_pr[9 * NTOK * 8];  // normalized probs per (stage, tok)
__device__ float g_WinT[512 * 72];    // [c][q]
__device__ float g_WoT[512 * 72];     // [c][q]
__device__ float g_M[81 * 64];        // M[i][j][d][e]
__device__ float g_cvec[81 * 8];      // W_in_i @ out_b_j
__device__ float g_Cbias[512];        // sum_j out_b_j
__device__ float g_cbn[9 * 8 * 128 * 8];  // normalized codebooks
__device__ float g_cn[9 * 8 * 128];       // raw norms
__device__ float g_cnt[72];
__device__ float g_ps[72];
__device__ float g_commit[1];

// ---------------- packed f32x2 helpers ----------------
__device__ __forceinline__ unsigned long long pack2(float lo, float hi) {
    unsigned long long r;
    asm("mov.b64 %0, {%1,%2};" : "=l"(r) : "f"(lo), "f"(hi));
    return r;
}
__device__ __forceinline__ void unpack2(unsigned long long v, float& lo, float& hi) {
    asm("mov.b64 {%0,%1}, %2;" : "=f"(lo), "=f"(hi) : "l"(v));
}
__device__ __forceinline__ unsigned long long fma2(unsigned long long a,
                                                   unsigned long long b,
                                                   unsigned long long c) {
    unsigned long long r;
    asm("fma.rn.f32x2 %0, %1, %2, %3;" : "=l"(r) : "l"(a), "l"(b), "l"(c));
    return r;
}
__device__ __forceinline__ unsigned long long add2(unsigned long long a,
                                                   unsigned long long b) {
    unsigned long long r;
    asm("add.rn.f32x2 %0, %1, %2;" : "=l"(r) : "l"(a), "l"(b));
    return r;
}

// ================================================================
// prep: weight-norm weights, codebook norms, Cbias, zeros, AND the
// cross matrices M/cvec recomputed from raw inputs (bit-identical to
// the previous two-kernel version; merged so kC is launch #4).
// ================================================================
__global__ void prep_kernel(const float* __restrict__ in_v, const float* __restrict__ in_g,
                            const float* __restrict__ out_v, const float* __restrict__ out_g,
                            const float* __restrict__ out_b, const float* __restrict__ cb) {
    int tid = blockIdx.x * blockDim.x + threadIdx.x;
    if (tid < 72) {
        const float* v = in_v + (size_t)tid * 512;
        float s = 0.f;
        for (int c = 0; c < 512; c++) s = fmaf(v[c], v[c], s);
        float inv = in_g[tid] / sqrtf(s);
        for (int c = 0; c < 512; c++) g_WinT[c * 72 + tid] = v[c] * inv;
    } else if (tid < 72 + 4608) {
        int rid = tid - 72;                       // j*512 + c
        int j = rid >> 9, c = rid & 511;
        const float* v = out_v + (size_t)rid * 8;
        float s = 0.f;
#pragma unroll
        for (int d = 0; d < 8; d++) s = fmaf(v[d], v[d], s);
        float inv = out_g[rid] / sqrtf(s);
#pragma unroll
        for (int d = 0; d < 8; d++) g_WoT[c * 72 + j * 8 + d] = v[d] * inv;
    } else if (tid < 4680 + 512) {
        int c = tid - 4680;
        float s = 0.f;
        for (int j = 0; j < 9; j++) s += out_b[j * 512 + c];
        g_Cbias[c] = s;
    } else if (tid < 5192 + 9216) {
        int rid = tid - 5192;                     // i*1024 + e*128 + k
        const float* v = cb + (size_t)rid * 8;
        float s = 0.f;
#pragma unroll
        for (int d = 0; d < 8; d++) s = fmaf(v[d], v[d], s);
        float rawn = sqrtf(s);
        float m = fmaxf(rawn, 1e-12f);
#pragma unroll
        for (int d = 0; d < 8; d++) g_cbn[rid * 8 + d] = v[d] / m;
        g_cn[rid] = rawn;
    } else if (tid < 14408 + 145) {
        int r = tid - 14408;
        if (r < 72) g_cnt[r] = 0.f;
        else if (r < 144) g_ps[r - 72] = 0.f;
        else g_commit[0] = 0.f;
    } else if (tid < 14553 + 5184) {
        // M[i][j][d][e] = sum_c Win[i8+d][c] * Wout_j[c][e], from raw inputs
        int r = tid - 14553;
        int ij = r >> 6, de = r & 63;
        int i = ij / 9, j = ij % 9, d = de >> 3, e = de & 7;
        const float* vi = in_v + (size_t)(i * 8 + d) * 512;
        float s = 0.f;
        for (int c = 0; c < 512; c++) s = fmaf(vi[c], vi[c], s);
        float inv_in = in_g[i * 8 + d] / sqrtf(s);
        float acc = 0.f;
        for (int c = 0; c < 512; c++) {
            const float* vo = out_v + ((size_t)j * 512 + c) * 8;
            float so = 0.f;
#pragma unroll
            for (int dd = 0; dd < 8; dd++) so = fmaf(vo[dd], vo[dd], so);
            float wo = vo[e] * (out_g[j * 512 + c] / sqrtf(so));
            acc = fmaf(vi[c] * inv_in, wo, acc);
        }
        g_M[ij * 64 + d * 8 + e] = acc;
    } else if (tid < 19737 + 648) {
        // cvec[i][j][d] = sum_c Win[i8+d][c] * out_b[j][c]
        int r = tid - 19737;
        int ij = r >> 3, d = r & 7;
        int i = ij / 9, j = ij % 9;
        const float* vi = in_v + (size_t)(i * 8 + d) * 512;
        float s = 0.f;
        for (int c = 0; c < 512; c++) s = fmaf(vi[c], vi[c], s);
        float inv_in = in_g[i * 8 + d] / sqrtf(s);
        float acc = 0.f;
        for (int c = 0; c < 512; c++)
            acc = fmaf(vi[c] * inv_in, out_b[j * 512 + c], acc);
        g_cvec[ij * 8 + d] = acc;
    }
}

// ================================================================
// kernel A: P = W_in_all @ z + in_b.
// grid 512: (qh = bid&1: 36-q half) x (256-token tile).
// Thread: 1 token, 18 packed accumulators (36 regs) -> 3 blocks/SM,
// 24 warps/SM, smem 73.7KB x3 = 221KB. z read 2x, qh-adjacent blocks
// share z tiles in L2.
// ================================================================
__global__ __launch_bounds__(256, 3) void kA_kernel(const float* __restrict__ z,
                                                    const float* __restrict__ in_b) {
    extern __shared__ float ws[];     // 512*36 floats
    int tid = threadIdx.x;
    int qh = blockIdx.x & 1;
    int tile = blockIdx.x >> 1;

    // stage half-weights: ws[c*36 + f4] <- g_WinT[c*72 + qh*36 ...]
#pragma unroll
    for (int u = 0; u < 18; u++) {
        int g = tid + u * 256;        // 4608 float4
        int c = g / 9, f = g % 9;
        ((float4*)ws)[c * 9 + f] = *(const float4*)(g_WinT + c * 72 + qh * 36 + f * 4);
    }
    __syncthreads();

    int tok = tile * 256 + tid;
    int b = tok >> 12, t = tok & 4095;

    unsigned long long acc[18];
#pragma unroll
    for (int m = 0; m < 18; m++) acc[m] = 0ULL;

    const float* zp = z + (size_t)b * 512 * 4096 + t;
#pragma unroll 1
    for (int c0 = 0; c0 < 512; c0 += 8) {
        float zr[8];
#pragma unroll
        for (int u = 0; u < 8; u++) zr[u] = zp[(size_t)(c0 + u) * 4096];
#pragma unroll
        for (int cc = 0; cc < 8; cc++) {
            unsigned long long z2 = pack2(zr[cc], zr[cc]);
            const ulonglong2* wrow = (const ulonglong2*)(ws + (c0 + cc) * 36);
#pragma unroll
            for (int u = 0; u < 9; u++) {
                ulonglong2 w = wrow[u];
                acc[2 * u]     = fma2(w.x, z2, acc[2 * u]);
                acc[2 * u + 1] = fma2(w.y, z2, acc[2 * u + 1]);
            }
        }
    }
#pragma unroll
    for (int m = 0; m < 18; m++) {
        int q = qh * 36 + 2 * m;
        float lo, hi;
        unpack2(acc[m], lo, hi);
        g_P[(size_t)q * NTOK + tok]       = lo + __ldg(&in_b[q]);
        g_P[(size_t)(q + 1) * NTOK + tok] = hi + __ldg(&in_b[q + 1]);
    }
}

// ================================================================
// kernel B: per-token sequential RVQ, 1 thread/token, stages unrolled,
// q history in registers. grid 256 x 256.
// ================================================================
__global__ __launch_bounds__(256, 2) void kB_kernel(const float* __restrict__ r_w1,
                                                    const float* __restrict__ r_b1,
                                                    const float* __restrict__ r_w2,
                                                    const float* __restrict__ r_b2,
                                                    float* __restrict__ out) {
    extern __shared__ float4 sm4[];
    float4* s_cb = sm4;                       // 2056 float4 (expert stride 1028 floats)
    float* fb = (float*)(sm4 + 2056);
    float* s_M    = fb;                       // 5184
    float* s_cvec = s_M + 5184;               // 648
    float* s_w1   = s_cvec + 648;             // 576
    float* s_b1   = s_w1 + 576;               // 72
    float* s_w2   = s_b1 + 72;                // 576
    float* s_b2   = s_w2 + 576;               // 72
    float* s_red  = s_b2 + 72;                // 8

    int tid = threadIdx.x, lane = tid & 31, wid = tid >> 5;
    int tok = blockIdx.x * 256 + tid;
    int b = tok >> 12, t = tok & 4095;

    // one-time staging (ordered by the stage-0 barrier below)
    for (int j = tid; j < 5184; j += 256) s_M[j] = g_M[j];
    for (int j = tid; j < 648; j += 256) s_cvec[j] = g_cvec[j];
    for (int j = tid; j < 576; j += 256) { s_w1[j] = r_w1[j]; s_w2[j] = r_w2[j]; }
    if (tid < 72) { s_b1[tid] = r_b1[tid]; s_b2[tid] = r_b2[tid]; }

    float q_hist[72];
    float commit_loc = 0.f;
    float* out_codes = out + CODES_OFF;
    float* out_lat = out + LAT_OFF;

#pragma unroll
    for (int i = 0; i < 9; i++) {
        __syncthreads();
        {   // stage codebook into padded smem
            const float4* src = (const float4*)(g_cbn + (size_t)i * 8192);
#pragma unroll
            for (int j = 0; j < 8; j++) {
                int g = tid + j * 256;
                int e = g >> 8, r = g & 255;
                s_cb[e * 257 + r] = src[g];
            }
        }
        __syncthreads();

        // z_e = P_i - sum_{j<i} (M_ij q_j + c_ij), q from registers
        float ze[8];
#pragma unroll
        for (int d = 0; d < 8; d++) ze[d] = g_P[(size_t)(i * 8 + d) * NTOK + tok];
#pragma unroll
        for (int j = 0; j < i; j++) {
            const float* Mij = s_M + (i * 9 + j) * 64;
            const float* cij = s_cvec + (i * 9 + j) * 8;
#pragma unroll
            for (int d = 0; d < 8; d++) {
                float s = cij[d];
#pragma unroll
                for (int e = 0; e < 8; e++) s = fmaf(Mij[d * 8 + e], q_hist[j * 8 + e], s);
                ze[d] -= s;
            }
        }

        // latents output
        {
            float4* lp = (float4*)(out_lat + ((size_t)((b * 9 + i) * 4096 + t)) * 8);
            lp[0] = make_float4(ze[0], ze[1], ze[2], ze[3]);
            lp[1] = make_float4(ze[4], ze[5], ze[6], ze[7]);
        }

        // router (weights in smem, broadcast)
        float h[8];
#pragma unroll
        for (int hh = 0; hh < 8; hh++) {
            float s = s_b1[i * 8 + hh];
#pragma unroll
            for (int d = 0; d < 8; d++) s = fmaf(s_w1[(i * 8 + hh) * 8 + d], ze[d], s);
            h[hh] = fmaxf(s, 0.f);
        }
        float lg[8];
        float lmax = -3.4e38f;
        int estar = 0;
#pragma unroll
        for (int e = 0; e < 8; e++) {
            float s = s_b2[i * 8 + e];
#pragma unroll
            for (int hh = 0; hh < 8; hh++) s = fmaf(s_w2[(i * 8 + e) * 8 + hh], h[hh], s);
            lg[e] = s;
            if (s > lmax) { lmax = s; estar = e; }
        }

        // normalized probs -> global (aux loss computed by kR)
        float pr[8], psum = 0.f;
#pragma unroll
        for (int e = 0; e < 8; e++) { pr[e] = expf(lg[e] - lmax); psum += pr[e]; }
        float pinv = 1.f / psum;
        {
            float4* pp = (float4*)(g_pr + ((size_t)i * NTOK + tok) * 8);
            pp[0] = make_float4(pr[0] * pinv, pr[1] * pinv, pr[2] * pinv, pr[3] * pinv);
            pp[1] = make_float4(pr[4] * pinv, pr[5] * pinv, pr[6] * pinv, pr[7] * pinv);
        }

        // nearest neighbor: argmax_k ze . cbn_k  (|cbn|=1, scale-invariant)
        const float4* cpe = s_cb + estar * 257;
        float best = -3.4e38f;
        int bk = 0;
#pragma unroll 4
        for (int k = 0; k < 128; k++) {
            float4 a = cpe[2 * k], c = cpe[2 * k + 1];
            float dt = fmaf(ze[0], a.x, fmaf(ze[1], a.y, fmaf(ze[2], a.z, ze[3] * a.w)));
            dt = fmaf(ze[4], c.x, fmaf(ze[5], c.y, fmaf(ze[6], c.z, fmaf(ze[7], c.w, dt))));
            if (dt > best) { best = dt; bk = k; }
        }

        float cn = __ldg(&g_cn[i * 1024 + estar * 128 + bk]);
        float4 a = cpe[2 * bk], c = cpe[2 * bk + 1];
        float q[8] = { a.x * cn, a.y * cn, a.z * cn, a.w * cn,
                       c.x * cn, c.y * cn, c.z * cn, c.w * cn };
#pragma unroll
        for (int d = 0; d < 8; d++) {
            q_hist[i * 8 + d] = q[d];
            g_Q[(size_t)(i * 8 + d) * NTOK + tok] = q[d];
            float df = ze[d] - q[d];
            commit_loc = fmaf(df, df, commit_loc);
        }
        out_codes[(size_t)(b * 9 + i) * 4096 + t] = (float)(bk + 128 * estar);
    }

    // reduce commitment
    commit_loc += __shfl_xor_sync(0xffffffffu, commit_loc, 16);
    commit_loc += __shfl_xor_sync(0xffffffffu, commit_loc, 8);
    commit_loc += __shfl_xor_sync(0xffffffffu, commit_loc, 4);
    commit_loc += __shfl_xor_sync(0xffffffffu, commit_loc, 2);
    commit_loc += __shfl_xor_sync(0xffffffffu, commit_loc, 1);
    __syncthreads();
    if (lane == 0) s_red[wid] = commit_loc;
    __syncthreads();
    if (tid == 0) {
        float s = 0.f;
        for (int w = 0; w < 8; w++) s += s_red[w];
        atomicAdd(&g_commit[0], s);
    }
}

// ================================================================
// kernel C: z_q = W_out_cat @ Q + Cbias.
// grid 1024: (cq = bid&3: 128-c quarter) x (256-token tile).
// Thread: 1 token, q2[36] packed regs; smem 128x72 weights + bias
// (37.4KB). Launch #4 -> profiled this round.
// ================================================================
__global__ __launch_bounds__(256, 2) void kC_kernel(float* __restrict__ out) {
    extern __shared__ float sm[];          // 128*72 + 128 floats
    float* ws = sm;
    float* cbias = sm + 9216;
    int tid = threadIdx.x;
    int cq = blockIdx.x & 3;
    int tile = blockIdx.x >> 2;
    int cbase = cq * 128;

    for (int g = tid; g < 128 * 18; g += 256)  // 2304 float4, contiguous
        ((float4*)ws)[g] = *(const float4*)(g_WoT + (size_t)cbase * 72 + g * 4);
    if (tid < 128) cbias[tid] = g_Cbias[cbase + tid];
    __syncthreads();

    int tok = tile * 256 + tid;
    int b = tok >> 12, t = tok & 4095;

    unsigned long long q2[36];
#pragma unroll
    for (int m = 0; m < 36; m++)
        q2[m] = pack2(g_Q[(size_t)(2 * m) * NTOK + tok],
                      g_Q[(size_t)(2 * m + 1) * NTOK + tok]);

    float* op = out + (size_t)b * 512 * 4096 + (size_t)cbase * 4096 + t;
#pragma unroll 2
    for (int cr = 0; cr < 128; cr++) {
        const ulonglong2* wr = (const ulonglong2*)(ws + cr * 72);
        unsigned long long ac0 = 0ULL, ac1 = 0ULL, ac2 = 0ULL, ac3 = 0ULL;
#pragma unroll
        for (int m = 0; m < 9; m++) {
            ulonglong2 w0 = wr[2 * m];
            ulonglong2 w1 = wr[2 * m + 1];
            ac0 = fma2(w0.x, q2[4 * m], ac0);
            ac1 = fma2(w0.y, q2[4 * m + 1], ac1);
            ac2 = fma2(w1.x, q2[4 * m + 2], ac2);
            ac3 = fma2(w1.y, q2[4 * m + 3], ac3);
        }
        unsigned long long s = add2(add2(ac0, ac1), add2(ac2, ac3));
        float lo, hi;
        unpack2(s, lo, hi);
        op[(size_t)cr * 4096] = lo + hi + cbias[cr];
    }
}

// ================================================================
// kernel R: reduce g_pr -> per-(stage,expert) prob sums + argmax counts
// ================================================================
__global__ void kR_kernel() {
    int i = blockIdx.x >> 5, chunk = blockIdx.x & 31;
    int tid = threadIdx.x, lane = tid & 31;
    float ps[8] = {0, 0, 0, 0, 0, 0, 0, 0};
    float cnt[8] = {0, 0, 0, 0, 0, 0, 0, 0};
    const float4* base = (const float4*)(g_pr + (size_t)i * NTOK * 8);
    int tok0 = chunk * 2048 + tid * 8;
#pragma unroll
    for (int u = 0; u < 8; u++) {
        int tok = tok0 + u;
        float4 v0 = base[tok * 2], v1 = base[tok * 2 + 1];
        float v[8] = {v0.x, v0.y, v0.z, v0.w, v1.x, v1.y, v1.z, v1.w};
        int am = 0;
        float m = v[0];
#pragma unroll
        for (int e = 1; e < 8; e++) if (v[e] > m) { m = v[e]; am = e; }
#pragma unroll
        for (int e = 0; e < 8; e++) {
            ps[e] += v[e];
            cnt[e] += (am == e) ? 1.f : 0.f;
        }
    }
#pragma unroll
    for (int e = 0; e < 8; e++) {
        for (int s = 16; s; s >>= 1) {
            ps[e] += __shfl_xor_sync(0xffffffffu, ps[e], s);
            cnt[e] += __shfl_xor_sync(0xffffffffu, cnt[e], s);
        }
    }
    if (lane == 0) {
#pragma unroll
        for (int e = 0; e < 8; e++) {
            atomicAdd(&g_ps[i * 8 + e], ps[e]);
            atomicAdd(&g_cnt[i * 8 + e], cnt[e]);
        }
    }
}

// ================================================================
// final: losses
// ================================================================
__global__ void kF_kernel(float* __restrict__ out) {
    __shared__ float sa[72];
    int tid = threadIdx.x;
    if (tid < 72) sa[tid] = g_cnt[tid] * g_ps[tid];
    __syncthreads();
    if (tid == 0) {
        float aux = 0.f;
        for (int q = 0; q < 72; q++) aux += sa[q];
        aux *= (1.f / 65536.f) * (1.f / 65536.f);
        float cm = g_commit[0] / 524288.f;    // /(16*4096*8)
        out[COMMIT_OFF] = cm;
        out[COMMIT_OFF + 1] = cm;             // codebook_loss == commitment_loss numerically
        out[COMMIT_OFF + 2] = aux;
    }
}

// ================================================================
extern "C" void kernel_launch(void* const* d_in, const int* in_sizes, int n_in,
                              void* d_out, int out_size) {
    const float* z     = (const float*)d_in[0];
    const float* in_v  = (const float*)d_in[1];
    const float* in_g  = (const float*)d_in[2];
    const float* in_b  = (const float*)d_in[3];
    const float* out_v = (const float*)d_in[4];
    const float* out_g = (const float*)d_in[5];
    const float* out_b = (const float*)d_in[6];
    const float* r_w1  = (const float*)d_in[7];
    const float* r_b1  = (const float*)d_in[8];
    const float* r_w2  = (const float*)d_in[9];
    const float* r_b2  = (const float*)d_in[10];
    const float* cb    = (const float*)d_in[11];
    float* out = (float*)d_out;

    cudaFuncSetAttribute(kA_kernel, cudaFuncAttributeMaxDynamicSharedMemorySize, 73728);
    cudaFuncSetAttribute(kB_kernel, cudaFuncAttributeMaxDynamicSharedMemorySize, 61440);
    cudaFuncSetAttribute(kC_kernel, cudaFuncAttributeMaxDynamicSharedMemorySize, 37376);

    // launch order: prep(1) kA(2) kB(3) kC(4=profiled) kR(5) kF(6)
    prep_kernel<<<80, 256>>>(in_v, in_g, out_v, out_g, out_b, cb);
    kA_kernel<<<512, 256, 73728>>>(z, in_b);
    kB_kernel<<<256, 256, 61440>>>(r_w1, r_b1, r_w2, r_b2, out);
    kC_kernel<<<1024, 256, 37376>>>(out);
    kR_kernel<<<288, 256>>>();
    kF_kernel<<<1, 128>>>(out);
}

// round 14
// speedup vs baseline: 1.3899x; 1.3899x over previous
#include <cuda_runtime.h>
#include <math.h>

#define NTOK 65536
#define CODES_OFF 33554432
#define LAT_OFF   34144256
#define COMMIT_OFF 38862848

// ---------------- device scratch (no allocation) ----------------
__device__ float g_P[72 * NTOK];      // [q][tok], q = i*8+d
__device__ float g_Q[72 * NTOK];      // selected raw code vecs, [q][tok]
__device__ float g_pr[9 * NTOK * 8];  // normalized probs per (stage, tok)
__device__ float g_WinT[512 * 72];    // [c][q]
__device__ float g_WoT[512 * 72];     // [c][q]
__device__ float g_M[81 * 64];        // M[i][j][d][e]
__device__ float g_cvec[81 * 8];      // W_in_i @ out_b_j
__device__ float g_Cbias[512];        // sum_j out_b_j
__device__ float g_cbn[9 * 8 * 128 * 8];  // normalized codebooks
__device__ float g_cn[9 * 8 * 128];       // raw norms
__device__ float g_cnt[72];
__device__ float g_ps[72];
__device__ float g_commit[1];

// ---------------- packed f32x2 helpers ----------------
__device__ __forceinline__ unsigned long long pack2(float lo, float hi) {
    unsigned long long r;
    asm("mov.b64 %0, {%1,%2};" : "=l"(r) : "f"(lo), "f"(hi));
    return r;
}
__device__ __forceinline__ void unpack2(unsigned long long v, float& lo, float& hi) {
    asm("mov.b64 {%0,%1}, %2;" : "=f"(lo), "=f"(hi) : "l"(v));
}
__device__ __forceinline__ unsigned long long fma2(unsigned long long a,
                                                   unsigned long long b,
                                                   unsigned long long c) {
    unsigned long long r;
    asm("fma.rn.f32x2 %0, %1, %2, %3;" : "=l"(r) : "l"(a), "l"(b), "l"(c));
    return r;
}
__device__ __forceinline__ unsigned long long add2(unsigned long long a,
                                                   unsigned long long b) {
    unsigned long long r;
    asm("add.rn.f32x2 %0, %1, %2;" : "=l"(r) : "l"(a), "l"(b));
    return r;
}

// ================================================================
// prep1: weight-norm weights (transposed), codebook norms, Cbias, zeros
// ================================================================
__global__ void prep1_kernel(const float* __restrict__ in_v, const float* __restrict__ in_g,
                             const float* __restrict__ out_v, const float* __restrict__ out_g,
                             const float* __restrict__ out_b, const float* __restrict__ cb) {
    int tid = blockIdx.x * blockDim.x + threadIdx.x;
    if (tid < 72) {
        const float* v = in_v + (size_t)tid * 512;
        float s = 0.f;
        for (int c = 0; c < 512; c++) s = fmaf(v[c], v[c], s);
        float inv = in_g[tid] / sqrtf(s);
        for (int c = 0; c < 512; c++) g_WinT[c * 72 + tid] = v[c] * inv;
    } else if (tid < 72 + 4608) {
        int rid = tid - 72;                       // j*512 + c
        int j = rid >> 9, c = rid & 511;
        const float* v = out_v + (size_t)rid * 8;
        float s = 0.f;
#pragma unroll
        for (int d = 0; d < 8; d++) s = fmaf(v[d], v[d], s);
        float inv = out_g[rid] / sqrtf(s);
#pragma unroll
        for (int d = 0; d < 8; d++) g_WoT[c * 72 + j * 8 + d] = v[d] * inv;
    } else if (tid < 4680 + 512) {
        int c = tid - 4680;
        float s = 0.f;
        for (int j = 0; j < 9; j++) s += out_b[j * 512 + c];
        g_Cbias[c] = s;
    } else if (tid < 5192 + 9216) {
        int rid = tid - 5192;                     // i*1024 + e*128 + k
        const float* v = cb + (size_t)rid * 8;
        float s = 0.f;
#pragma unroll
        for (int d = 0; d < 8; d++) s = fmaf(v[d], v[d], s);
        float rawn = sqrtf(s);
        float m = fmaxf(rawn, 1e-12f);
#pragma unroll
        for (int d = 0; d < 8; d++) g_cbn[rid * 8 + d] = v[d] / m;
        g_cn[rid] = rawn;
    } else if (tid < 14408 + 145) {
        int r = tid - 14408;
        if (r < 72) g_cnt[r] = 0.f;
        else if (r < 144) g_ps[r - 72] = 0.f;
        else g_commit[0] = 0.f;
    }
}

// ================================================================
// prep2: M[i][j] = W_in_i @ W_out_j, cvec[i][j] = W_in_i @ out_b_j
// ================================================================
__global__ void prep2_kernel(const float* __restrict__ out_b) {
    int ij = blockIdx.x;              // i*9+j
    int i = ij / 9, j = ij % 9;
    int tid = threadIdx.x;            // 72 threads
    if (tid < 64) {
        int d = tid >> 3, e = tid & 7;
        float s = 0.f;
        for (int c = 0; c < 512; c++)
            s = fmaf(g_WinT[c * 72 + i * 8 + d], g_WoT[c * 72 + j * 8 + e], s);
        g_M[ij * 64 + d * 8 + e] = s;
    } else {
        int d = tid - 64;
        float s = 0.f;
        for (int c = 0; c < 512; c++)
            s = fmaf(g_WinT[c * 72 + i * 8 + d], out_b[j * 512 + c], s);
        g_cvec[ij * 8 + d] = s;
    }
}

// pad kernel: positions kA as the 4th launch so ncu's capture window hits it
__global__ void pad_kernel() {}

// ================================================================
// kernel A: P = W_in_all @ z + in_b.
// grid 256: block = (token tile of 512) x (q-half of 36).
// Thread: 2 adjacent tokens x 18 q-pairs, 36 packed accumulators.
// smem: 512 x 36 half-weights (73728 B).   [R10 version, 543us run]
// ================================================================
__global__ __launch_bounds__(256) void kA_kernel(const float* __restrict__ z,
                                                 const float* __restrict__ in_b) {
    extern __shared__ float ws[];     // 512*36 floats
    int tid = threadIdx.x;
    int qh = blockIdx.x & 1;
    int tileBase = (blockIdx.x >> 1) * 512;

    // stage half-weights: ws[c*36 + j] = g_WinT[c*72 + qh*36 + j]
    for (int g = tid; g < 512 * 9; g += 256) {
        int c = g / 9, j4 = g % 9;
        ((float4*)ws)[c * 9 + j4] = *(const float4*)(g_WinT + c * 72 + qh * 36 + j4 * 4);
    }
    __syncthreads();

    int tok0 = tileBase + 2 * tid;
    int b = tok0 >> 12, t0 = tok0 & 4095;

    unsigned long long a0[18], a1[18];
#pragma unroll
    for (int m = 0; m < 18; m++) { a0[m] = 0ULL; a1[m] = 0ULL; }

    const float* zp = z + (size_t)b * 512 * 4096 + t0;
#pragma unroll 1
    for (int c0 = 0; c0 < 512; c0 += 8) {
        float2 zv[8];
#pragma unroll
        for (int cc = 0; cc < 8; cc++)
            zv[cc] = *(const float2*)(zp + (size_t)(c0 + cc) * 4096);
#pragma unroll
        for (int cc = 0; cc < 8; cc++) {
            unsigned long long za = pack2(zv[cc].x, zv[cc].x);
            unsigned long long zb = pack2(zv[cc].y, zv[cc].y);
            const ulonglong2* wrow = (const ulonglong2*)(ws + (c0 + cc) * 36);
#pragma unroll
            for (int m = 0; m < 9; m++) {
                ulonglong2 w = wrow[m];
                a0[2 * m]     = fma2(w.x, za, a0[2 * m]);
                a0[2 * m + 1] = fma2(w.y, za, a0[2 * m + 1]);
                a1[2 * m]     = fma2(w.x, zb, a1[2 * m]);
                a1[2 * m + 1] = fma2(w.y, zb, a1[2 * m + 1]);
            }
        }
    }
#pragma unroll
    for (int m = 0; m < 18; m++) {
        int q = qh * 36 + 2 * m;
        float l0, h0, l1, h1;
        unpack2(a0[m], l0, h0);      // token0: q, q+1
        unpack2(a1[m], l1, h1);      // token1
        float be = __ldg(&in_b[q]), bo = __ldg(&in_b[q + 1]);
        *(float2*)&g_P[(size_t)q * NTOK + tok0]       = make_float2(l0 + be, l1 + be);
        *(float2*)&g_P[(size_t)(q + 1) * NTOK + tok0] = make_float2(h0 + bo, h1 + bo);
    }
}

// ================================================================
// kernel B: per-token sequential RVQ, 1 thread/token, stages unrolled,
// q history in registers. grid 256 x 256.   [R10 version, 543us run]
// ================================================================
__global__ __launch_bounds__(256, 2) void kB_kernel(const float* __restrict__ r_w1,
                                                    const float* __restrict__ r_b1,
                                                    const float* __restrict__ r_w2,
                                                    const float* __restrict__ r_b2,
                                                    float* __restrict__ out) {
    extern __shared__ float4 sm4[];
    float4* s_cb = sm4;                       // 2056 float4 (expert stride 1028 floats)
    float* fb = (float*)(sm4 + 2056);
    float* s_M    = fb;                       // 5184
    float* s_cvec = s_M + 5184;               // 648
    float* s_w1   = s_cvec + 648;             // 576
    float* s_b1   = s_w1 + 576;               // 72
    float* s_w2   = s_b1 + 72;                // 576
    float* s_b2   = s_w2 + 576;               // 72
    float* s_red  = s_b2 + 72;                // 8

    int tid = threadIdx.x, lane = tid & 31, wid = tid >> 5;
    int tok = blockIdx.x * 256 + tid;
    int b = tok >> 12, t = tok & 4095;

    // one-time staging (ordered by the stage-0 barrier below)
    for (int j = tid; j < 5184; j += 256) s_M[j] = g_M[j];
    for (int j = tid; j < 648; j += 256) s_cvec[j] = g_cvec[j];
    for (int j = tid; j < 576; j += 256) { s_w1[j] = r_w1[j]; s_w2[j] = r_w2[j]; }
    if (tid < 72) { s_b1[tid] = r_b1[tid]; s_b2[tid] = r_b2[tid]; }

    float q_hist[72];
    float commit_loc = 0.f;
    float* out_codes = out + CODES_OFF;
    float* out_lat = out + LAT_OFF;

#pragma unroll
    for (int i = 0; i < 9; i++) {
        __syncthreads();
        {   // stage codebook into padded smem
            const float4* src = (const float4*)(g_cbn + (size_t)i * 8192);
#pragma unroll
            for (int j = 0; j < 8; j++) {
                int g = tid + j * 256;
                int e = g >> 8, r = g & 255;
                s_cb[e * 257 + r] = src[g];
            }
        }
        __syncthreads();

        // z_e = P_i - sum_{j<i} (M_ij q_j + c_ij), q from registers
        float ze[8];
#pragma unroll
        for (int d = 0; d < 8; d++) ze[d] = g_P[(size_t)(i * 8 + d) * NTOK + tok];
#pragma unroll
        for (int j = 0; j < i; j++) {
            const float* Mij = s_M + (i * 9 + j) * 64;
            const float* cij = s_cvec + (i * 9 + j) * 8;
#pragma unroll
            for (int d = 0; d < 8; d++) {
                float s = cij[d];
#pragma unroll
                for (int e = 0; e < 8; e++) s = fmaf(Mij[d * 8 + e], q_hist[j * 8 + e], s);
                ze[d] -= s;
            }
        }

        // latents output
        {
            float4* lp = (float4*)(out_lat + ((size_t)((b * 9 + i) * 4096 + t)) * 8);
            lp[0] = make_float4(ze[0], ze[1], ze[2], ze[3]);
            lp[1] = make_float4(ze[4], ze[5], ze[6], ze[7]);
        }

        // router (weights in smem, broadcast)
        float h[8];
#pragma unroll
        for (int hh = 0; hh < 8; hh++) {
            float s = s_b1[i * 8 + hh];
#pragma unroll
            for (int d = 0; d < 8; d++) s = fmaf(s_w1[(i * 8 + hh) * 8 + d], ze[d], s);
            h[hh] = fmaxf(s, 0.f);
        }
        float lg[8];
        float lmax = -3.4e38f;
        int estar = 0;
#pragma unroll
        for (int e = 0; e < 8; e++) {
            float s = s_b2[i * 8 + e];
#pragma unroll
            for (int hh = 0; hh < 8; hh++) s = fmaf(s_w2[(i * 8 + e) * 8 + hh], h[hh], s);
            lg[e] = s;
            if (s > lmax) { lmax = s; estar = e; }
        }

        // normalized probs -> global (aux loss computed by kR)
        float pr[8], psum = 0.f;
#pragma unroll
        for (int e = 0; e < 8; e++) { pr[e] = expf(lg[e] - lmax); psum += pr[e]; }
        float pinv = 1.f / psum;
        {
            float4* pp = (float4*)(g_pr + ((size_t)i * NTOK + tok) * 8);
            pp[0] = make_float4(pr[0] * pinv, pr[1] * pinv, pr[2] * pinv, pr[3] * pinv);
            pp[1] = make_float4(pr[4] * pinv, pr[5] * pinv, pr[6] * pinv, pr[7] * pinv);
        }

        // nearest neighbor: argmax_k ze . cbn_k  (|cbn|=1, scale-invariant)
        const float4* cpe = s_cb + estar * 257;
        float best = -3.4e38f;
        int bk = 0;
#pragma unroll 4
        for (int k = 0; k < 128; k++) {
            float4 a = cpe[2 * k], c = cpe[2 * k + 1];
            float dt = fmaf(ze[0], a.x, fmaf(ze[1], a.y, fmaf(ze[2], a.z, ze[3] * a.w)));
            dt = fmaf(ze[4], c.x, fmaf(ze[5], c.y, fmaf(ze[6], c.z, fmaf(ze[7], c.w, dt))));
            if (dt > best) { best = dt; bk = k; }
        }

        float cn = __ldg(&g_cn[i * 1024 + estar * 128 + bk]);
        float4 a = cpe[2 * bk], c = cpe[2 * bk + 1];
        float q[8] = { a.x * cn, a.y * cn, a.z * cn, a.w * cn,
                       c.x * cn, c.y * cn, c.z * cn, c.w * cn };
#pragma unroll
        for (int d = 0; d < 8; d++) {
            q_hist[i * 8 + d] = q[d];
            g_Q[(size_t)(i * 8 + d) * NTOK + tok] = q[d];
            float df = ze[d] - q[d];
            commit_loc = fmaf(df, df, commit_loc);
        }
        out_codes[(size_t)(b * 9 + i) * 4096 + t] = (float)(bk + 128 * estar);
    }

    // reduce commitment
    commit_loc += __shfl_xor_sync(0xffffffffu, commit_loc, 16);
    commit_loc += __shfl_xor_sync(0xffffffffu, commit_loc, 8);
    commit_loc += __shfl_xor_sync(0xffffffffu, commit_loc, 4);
    commit_loc += __shfl_xor_sync(0xffffffffu, commit_loc, 2);
    commit_loc += __shfl_xor_sync(0xffffffffu, commit_loc, 1);
    __syncthreads();
    if (lane == 0) s_red[wid] = commit_loc;
    __syncthreads();
    if (tid == 0) {
        float s = 0.f;
        for (int w = 0; w < 8; w++) s += s_red[w];
        atomicAdd(&g_commit[0], s);
    }
}

// ================================================================
// kernel R: reduce g_pr -> per-(stage,expert) prob sums + argmax counts
// ================================================================
__global__ void kR_kernel() {
    int i = blockIdx.x >> 5, chunk = blockIdx.x & 31;
    int tid = threadIdx.x, lane = tid & 31;
    float ps[8] = {0, 0, 0, 0, 0, 0, 0, 0};
    float cnt[8] = {0, 0, 0, 0, 0, 0, 0, 0};
    const float4* base = (const float4*)(g_pr + (size_t)i * NTOK * 8);
    int tok0 = chunk * 2048 + tid * 8;
#pragma unroll
    for (int u = 0; u < 8; u++) {
        int tok = tok0 + u;
        float4 v0 = base[tok * 2], v1 = base[tok * 2 + 1];
        float v[8] = {v0.x, v0.y, v0.z, v0.w, v1.x, v1.y, v1.z, v1.w};
        int am = 0;
        float m = v[0];
#pragma unroll
        for (int e = 1; e < 8; e++) if (v[e] > m) { m = v[e]; am = e; }
#pragma unroll
        for (int e = 0; e < 8; e++) {
            ps[e] += v[e];
            cnt[e] += (am == e) ? 1.f : 0.f;
        }
    }
#pragma unroll
    for (int e = 0; e < 8; e++) {
        for (int s = 16; s; s >>= 1) {
            ps[e] += __shfl_xor_sync(0xffffffffu, ps[e], s);
            cnt[e] += __shfl_xor_sync(0xffffffffu, cnt[e], s);
        }
    }
    if (lane == 0) {
#pragma unroll
        for (int e = 0; e < 8; e++) {
            atomicAdd(&g_ps[i * 8 + e], ps[e]);
            atomicAdd(&g_cnt[i * 8 + e], cnt[e]);
        }
    }
}

// ================================================================
// kernel C: z_q = W_out_cat @ Q + Cbias.
// grid 512: (cq = bid&3: 128-c quarter) x (512-token tile).
// Thread: 2 ADJACENT tokens concurrently. g_Q float2 loads give both
// tokens per 8B; repacked once into per-token q-pair chains that are
// bit-identical to the 543us kernel. Per cr: 18 LDS.128 feed 72 fma2.
// No launch_bounds: ~180 regs, 1 block/SM, no spill.
// ================================================================
__global__ void kC_kernel(float* __restrict__ out) {
    extern __shared__ float sm[];          // 128*72 + 128 floats
    float* ws = sm;
    float* cbias = sm + 9216;
    int tid = threadIdx.x;
    int cq = blockIdx.x & 3;
    int tile = blockIdx.x >> 2;
    int cbase = cq * 128;

    for (int g = tid; g < 128 * 18; g += 256)  // 2304 float4, contiguous
        ((float4*)ws)[g] = *(const float4*)(g_WoT + (size_t)cbase * 72 + g * 4);
    if (tid < 128) cbias[tid] = g_Cbias[cbase + tid];
    __syncthreads();

    int tok0 = tile * 512 + 2 * tid;           // two adjacent tokens
    int b = tok0 >> 12, t0 = tok0 & 4095;

    unsigned long long qa[36], qb[36];
#pragma unroll
    for (int m = 0; m < 36; m++) {
        float2 va = *(const float2*)&g_Q[(size_t)(2 * m) * NTOK + tok0];
        float2 vb = *(const float2*)&g_Q[(size_t)(2 * m + 1) * NTOK + tok0];
        qa[m] = pack2(va.x, vb.x);     // token0: (Q[2m], Q[2m+1])
        qb[m] = pack2(va.y, vb.y);     // token1
    }

    float* op = out + (size_t)b * 512 * 4096 + (size_t)cbase * 4096 + t0;
#pragma unroll 2
    for (int cr = 0; cr < 128; cr++) {
        const ulonglong2* wr = (const ulonglong2*)(ws + cr * 72);
        unsigned long long a0 = 0ULL, a1 = 0ULL, a2 = 0ULL, a3 = 0ULL;
        unsigned long long b0 = 0ULL, b1 = 0ULL, b2 = 0ULL, b3 = 0ULL;
#pragma unroll
        for (int m = 0; m < 9; m++) {
            ulonglong2 w0 = wr[2 * m];
            ulonglong2 w1 = wr[2 * m + 1];
            a0 = fma2(w0.x, qa[4 * m], a0);
            a1 = fma2(w0.y, qa[4 * m + 1], a1);
            a2 = fma2(w1.x, qa[4 * m + 2], a2);
            a3 = fma2(w1.y, qa[4 * m + 3], a3);
            b0 = fma2(w0.x, qb[4 * m], b0);
            b1 = fma2(w0.y, qb[4 * m + 1], b1);
            b2 = fma2(w1.x, qb[4 * m + 2], b2);
            b3 = fma2(w1.y, qb[4 * m + 3], b3);
        }
        unsigned long long sA = add2(add2(a0, a1), add2(a2, a3));
        unsigned long long sB = add2(add2(b0, b1), add2(b2, b3));
        float lo, hi, r0, r1;
        unpack2(sA, lo, hi); r0 = lo + hi + cbias[cr];
        unpack2(sB, lo, hi); r1 = lo + hi + cbias[cr];
        *(float2*)(op + (size_t)cr * 4096) = make_float2(r0, r1);
    }
}

// ================================================================
// final: losses
// ================================================================
__global__ void kF_kernel(float* __restrict__ out) {
    __shared__ float sa[72];
    int tid = threadIdx.x;
    if (tid < 72) sa[tid] = g_cnt[tid] * g_ps[tid];
    __syncthreads();
    if (tid == 0) {
        float aux = 0.f;
        for (int q = 0; q < 72; q++) aux += sa[q];
        aux *= (1.f / 65536.f) * (1.f / 65536.f);
        float cm = g_commit[0] / 524288.f;    // /(16*4096*8)
        out[COMMIT_OFF] = cm;
        out[COMMIT_OFF + 1] = cm;             // codebook_loss == commitment_loss numerically
        out[COMMIT_OFF + 2] = aux;
    }
}

// ================================================================
extern "C" void kernel_launch(void* const* d_in, const int* in_sizes, int n_in,
                              void* d_out, int out_size) {
    const float* z     = (const float*)d_in[0];
    const float* in_v  = (const float*)d_in[1];
    const float* in_g  = (const float*)d_in[2];
    const float* in_b  = (const float*)d_in[3];
    const float* out_v = (const float*)d_in[4];
    const float* out_g = (const float*)d_in[5];
    const float* out_b = (const float*)d_in[6];
    const float* r_w1  = (const float*)d_in[7];
    const float* r_b1  = (const float*)d_in[8];
    const float* r_w2  = (const float*)d_in[9];
    const float* r_b2  = (const float*)d_in[10];
    const float* cb    = (const float*)d_in[11];
    float* out = (float*)d_out;

    cudaFuncSetAttribute(kA_kernel, cudaFuncAttributeMaxDynamicSharedMemorySize, 73728);
    cudaFuncSetAttribute(kB_kernel, cudaFuncAttributeMaxDynamicSharedMemorySize, 61440);
    cudaFuncSetAttribute(kC_kernel, cudaFuncAttributeMaxDynamicSharedMemorySize, 37376);

    // launch order: prep1(1) prep2(2) pad(3) kA(4=profiled) kB kC kR kF
    prep1_kernel<<<57, 256>>>(in_v, in_g, out_v, out_g, out_b, cb);
    prep2_kernel<<<81, 72>>>(out_b);
    pad_kernel<<<1, 32>>>();
    kA_kernel<<<256, 256, 73728>>>(z, in_b);
    kB_kernel<<<256, 256, 61440>>>(r_w1, r_b1, r_w2, r_b2, out);
    kC_kernel<<<512, 256, 37376>>>(out);
    kR_kernel<<<288, 256>>>();
    kF_kernel<<<1, 128>>>(out);
}